// round 9
// baseline (speedup 1.0000x reference)
#include <cuda_runtime.h>
#include <cuda_fp16.h>
#include <cuda_bf16.h>
#include <mma.h>
#include <math.h>

using namespace nvcuda;

#define NN 100000
#define NE 1600000
#define FEAT 165
#define HID 128
#define KPAD 192          // K padded to 6 tiles of 32
#define NKT 6
#define NBT 196           // scan tiles (196 * 512 >= NN)
#define GEMM_NB 782       // ceil(100000/128)
#define FILL_NB 782       // 782*256 threads * 8 edges >= NE
#define CVTX_NB 18750     // 100000*192/4/256
#define CVTW_NB 24        // 192*128/4/256
#define CNT_NB 1563       // ceil(NE/4/256)

// ---------------- scratch (static __device__, allocation-free) ----------------
__device__ int            g_deg[NN];
__device__ float          g_dinv[NN];
__device__ int            g_rowptr[NN];
__device__ int            g_cursor[NN];
__device__ int            g_tile_ctr;
__device__ unsigned       g_tile_state[NBT];
__device__ int2           g_csr[NE];                     // (src, bits(w))
__device__ __nv_bfloat16  g_xb[(size_t)100096 * KPAD];   // x in bf16, padded (38.4MB)
__device__ __nv_bfloat16  g_w1b[KPAD * HID];             // W1 in bf16, padded
__device__ __half         g_xw[(size_t)NN * HID];        // x @ W1 in fp16 (25.6 MB)
__device__ float          g_z[NN * 2];

#define ST_AGG 0x40000000u
#define ST_PRE 0x80000000u
#define ST_VAL 0x3FFFFFFFu

// ---------------- init: zero degrees + scan state ----------------
__global__ void k_init() {
    int i = blockIdx.x * blockDim.x + threadIdx.x;
    if (i < NN) g_deg[i] = 0;
    if (i < NBT) g_tile_state[i] = 0;
    if (i == 0) g_tile_ctr = 0;
}

// ---------------- fused convert(x,W1 -> bf16) + degree count ----------------
__global__ void k_cvt_count(const float* __restrict__ x,
                            const float* __restrict__ W1,
                            const int* __restrict__ ei) {
    int b = blockIdx.x;
    if (b < CVTX_NB) {
        int t = b * 256 + threadIdx.x;        // 4.8M threads, 4 elems each
        int r = t / (KPAD / 4);
        int k0 = (t % (KPAD / 4)) * 4;
        __nv_bfloat16 o[4];
        #pragma unroll
        for (int j = 0; j < 4; j++) {
            int k = k0 + j;
            float v = (k < FEAT) ? x[(size_t)r * FEAT + k] : 0.f;
            o[j] = __float2bfloat16(v);
        }
        *(uint2*)&g_xb[(size_t)r * KPAD + k0] = *(uint2*)o;
    } else if (b < CVTX_NB + CVTW_NB) {
        int t = (b - CVTX_NB) * 256 + threadIdx.x;   // 6144 threads
        int k = t / (HID / 4);
        int n0 = (t % (HID / 4)) * 4;
        __nv_bfloat16 o[4];
        #pragma unroll
        for (int j = 0; j < 4; j++) {
            float v = (k < FEAT) ? W1[k * HID + n0 + j] : 0.f;
            o[j] = __float2bfloat16(v);
        }
        *(uint2*)&g_w1b[k * HID + n0] = *(uint2*)o;
    } else {
        int t = (b - CVTX_NB - CVTW_NB) * 256 + threadIdx.x;
        int e0 = t * 4;
        if (e0 < NE) {
            int4 d4 = *(const int4*)&ei[NE + e0];
            if (d4.x >= 0 && d4.x < NN) atomicAdd(&g_deg[d4.x], 1);
            if (d4.y >= 0 && d4.y < NN) atomicAdd(&g_deg[d4.y], 1);
            if (d4.z >= 0 && d4.z < NN) atomicAdd(&g_deg[d4.z], 1);
            if (d4.w >= 0 && d4.w < NN) atomicAdd(&g_deg[d4.w], 1);
        }
    }
}

// ---------------- single-pass scan (decoupled lookback) + dinv ----------------
__global__ void k_scan() {
    __shared__ int s[512];
    __shared__ int sh_bid;
    __shared__ int sh_excl;
    int t = threadIdx.x;
    if (t == 0) sh_bid = atomicAdd(&g_tile_ctr, 1);
    __syncthreads();
    int bid = sh_bid;
    int i = bid * 512 + t;
    int v = (i < NN) ? g_deg[i] : 0;
    if (i < NN) g_dinv[i] = rsqrtf((float)v + 1.0f);
    s[t] = v;
    __syncthreads();
    #pragma unroll
    for (int off = 1; off < 512; off <<= 1) {
        int u = (t >= off) ? s[t - off] : 0;
        __syncthreads();
        s[t] += u;
        __syncthreads();
    }
    int incl = s[t];
    int total = s[511];
    if (t == 0) {
        if (bid == 0) {
            __threadfence();
            atomicExch(&g_tile_state[0], ST_PRE | (unsigned)total);
            sh_excl = 0;
        } else {
            __threadfence();
            atomicExch(&g_tile_state[bid], ST_AGG | (unsigned)total);
            int excl = 0;
            for (int j = bid - 1; j >= 0; j--) {
                unsigned st;
                do { st = atomicAdd(&g_tile_state[j], 0u); } while (!(st & (ST_AGG | ST_PRE)));
                excl += (int)(st & ST_VAL);
                if (st & ST_PRE) break;
            }
            __threadfence();
            atomicExch(&g_tile_state[bid], ST_PRE | (unsigned)(excl + total));
            sh_excl = excl;
        }
    }
    __syncthreads();
    if (i < NN) {
        int rp = sh_excl + incl - v;
        g_rowptr[i] = rp;
        g_cursor[i] = rp;
    }
}

// ---------------- fused fill + GEMM1 (bf16 wmma, double-buffered) -----------
// GEMM: block 128x128, 8 warps each 32x64, K-tile 32, reg-prefetch pipeline
#define ASTR 48           // bf16 elems per As row (96B, 16B-aligned chunks)
#define BSTR 136          // bf16 elems per Bs row (272B)
#define AS_BYTES (128 * ASTR * 2)   // 12288
#define BS_BYTES (32 * BSTR * 2)    // 8704
#define SM_BYTES (2 * AS_BYTES + 2 * BS_BYTES)  // 41984

__global__ __launch_bounds__(256, 2) void k_fill_gemm(const int* __restrict__ ei) {
    __shared__ __align__(16) char smraw[SM_BYTES];

    int tid = threadIdx.x;

    if (blockIdx.x >= GEMM_NB) {
        // ---------- fill branch: 8 edges per thread, int4 reads ----------
        int t8 = (blockIdx.x - GEMM_NB) * 256 + tid;
        int e0 = t8 * 8;
        if (e0 < NE) {
            int4 sa = *(const int4*)&ei[e0];
            int4 sb = *(const int4*)&ei[e0 + 4];
            int4 da = *(const int4*)&ei[NE + e0];
            int4 db = *(const int4*)&ei[NE + e0 + 4];
            int src[8] = {sa.x, sa.y, sa.z, sa.w, sb.x, sb.y, sb.z, sb.w};
            int dst[8] = {da.x, da.y, da.z, da.w, db.x, db.y, db.z, db.w};
            float ds[8], dd[8];
            #pragma unroll
            for (int j = 0; j < 8; j++) {
                bool ok = (src[j] >= 0 && src[j] < NN && dst[j] >= 0 && dst[j] < NN);
                ds[j] = ok ? g_dinv[src[j]] : 0.f;
                dd[j] = ok ? g_dinv[dst[j]] : 0.f;
                if (!ok) dst[j] = -1;
            }
            #pragma unroll
            for (int j = 0; j < 8; j++) {
                if (dst[j] >= 0) {
                    int p = atomicAdd(&g_cursor[dst[j]], 1);
                    g_csr[p] = make_int2(src[j], __float_as_int(ds[j] * dd[j]));
                }
            }
        }
        return;
    }

    // ---------- GEMM branch ----------
    int w = tid >> 5;
    int lane = tid & 31;
    int warp_m = w & 3;
    int warp_n = w >> 2;
    int row0 = blockIdx.x * 128;

    char* AsBuf[2] = { smraw, smraw + AS_BYTES };
    char* BsBuf[2] = { smraw + 2 * AS_BYTES, smraw + 2 * AS_BYTES + BS_BYTES };

    // per-thread chunk coords (constant across tiles)
    int am[2], ac[2], bk[2], bc[2];
    #pragma unroll
    for (int i = 0; i < 2; i++) {
        int c = tid + i * 256;       // 0..511
        am[i] = c >> 2;  ac[i] = c & 3;    // As: row m, 16B chunk cc
        bk[i] = c >> 4;  bc[i] = c & 15;   // Bs: row k, 16B chunk cc
    }

    uint4 pa[2], pb[2];
    auto loadTile = [&](int kt) {
        #pragma unroll
        for (int i = 0; i < 2; i++) {
            pa[i] = *(const uint4*)&g_xb[(size_t)(row0 + am[i]) * KPAD + kt * 32 + ac[i] * 8];
            pb[i] = *(const uint4*)&g_w1b[(kt * 32 + bk[i]) * HID + bc[i] * 8];
        }
    };

    wmma::fragment<wmma::accumulator, 16, 16, 16, float> cf[2][4];
    #pragma unroll
    for (int mi = 0; mi < 2; mi++)
        #pragma unroll
        for (int ni = 0; ni < 4; ni++)
            wmma::fill_fragment(cf[mi][ni], 0.0f);

    loadTile(0);
    for (int kt = 0; kt < NKT; kt++) {
        int bsel = kt & 1;
        // store prefetched tile to smem
        #pragma unroll
        for (int i = 0; i < 2; i++) {
            *(uint4*)(AsBuf[bsel] + am[i] * (ASTR * 2) + ac[i] * 16) = pa[i];
            *(uint4*)(BsBuf[bsel] + bk[i] * (BSTR * 2) + bc[i] * 16) = pb[i];
        }
        __syncthreads();
        if (kt + 1 < NKT) loadTile(kt + 1);   // overlap LDG with MMA below

        const __nv_bfloat16* As = (const __nv_bfloat16*)AsBuf[bsel];
        const __nv_bfloat16* Bs = (const __nv_bfloat16*)BsBuf[bsel];
        #pragma unroll
        for (int ks = 0; ks < 2; ks++) {
            wmma::fragment<wmma::matrix_a, 16, 16, 16, __nv_bfloat16, wmma::row_major> af[2];
            wmma::fragment<wmma::matrix_b, 16, 16, 16, __nv_bfloat16, wmma::row_major> bf[4];
            #pragma unroll
            for (int mi = 0; mi < 2; mi++)
                wmma::load_matrix_sync(af[mi], As + (warp_m * 32 + mi * 16) * ASTR + ks * 16, ASTR);
            #pragma unroll
            for (int ni = 0; ni < 4; ni++)
                wmma::load_matrix_sync(bf[ni], Bs + (ks * 16) * BSTR + warp_n * 64 + ni * 16, BSTR);
            #pragma unroll
            for (int mi = 0; mi < 2; mi++)
                #pragma unroll
                for (int ni = 0; ni < 4; ni++)
                    wmma::mma_sync(cf[mi][ni], af[mi], bf[ni], cf[mi][ni]);
        }
    }
    __syncthreads();   // all MMA smem reads done; reuse smem as C stage

    float* Cs = (float*)smraw + w * 256;   // 1KB per warp
    #pragma unroll
    for (int mi = 0; mi < 2; mi++) {
        #pragma unroll
        for (int ni = 0; ni < 4; ni++) {
            wmma::store_matrix_sync(Cs, cf[mi][ni], 16, wmma::mem_row_major);
            __syncwarp();
            int fr = lane >> 1;
            int fc = (lane & 1) * 8;
            int r = row0 + warp_m * 32 + mi * 16 + fr;
            if (r < NN) {
                const float* src = &Cs[fr * 16 + fc];
                __half2 h0 = __floats2half2_rn(src[0], src[1]);
                __half2 h1 = __floats2half2_rn(src[2], src[3]);
                __half2 h2 = __floats2half2_rn(src[4], src[5]);
                __half2 h3 = __floats2half2_rn(src[6], src[7]);
                uint4 pk;
                pk.x = *(unsigned*)&h0; pk.y = *(unsigned*)&h1;
                pk.z = *(unsigned*)&h2; pk.w = *(unsigned*)&h3;
                *(uint4*)&g_xw[(size_t)r * HID + warp_n * 64 + ni * 16 + fc] = pk;
            }
            __syncwarp();
        }
    }
}

// ---------------- layer-1 aggregation, fused bias+relu+(@W2) ----------------
__global__ __launch_bounds__(256) void k_agg1(const float* __restrict__ b1,
                                              const float* __restrict__ W2) {
    __shared__ float w2s[HID * 2];
    int t = threadIdx.x;
    w2s[t] = W2[t];
    __syncthreads();

    int warp = t >> 5, lane = t & 31;
    int i = blockIdx.x * 8 + warp;
    if (i >= NN) return;

    const uint2* xw2 = (const uint2*)g_xw;
    float di = g_dinv[i];
    float sn = di * di;
    uint2 sv = xw2[(size_t)i * 32 + lane];
    float2 s0 = __half22float2(*(__half2*)&sv.x);
    float2 s1 = __half22float2(*(__half2*)&sv.y);
    float a0 = sn * s0.x, a1 = sn * s0.y, a2 = sn * s1.x, a3 = sn * s1.y;

    int e = g_rowptr[i];
    int end = e + g_deg[i];
    for (; e + 4 <= end; e += 4) {
        int2 c0 = g_csr[e],     c1 = g_csr[e + 1];
        int2 c2 = g_csr[e + 2], c3 = g_csr[e + 3];
        uint2 v0 = xw2[(size_t)c0.x * 32 + lane];
        uint2 v1 = xw2[(size_t)c1.x * 32 + lane];
        uint2 v2 = xw2[(size_t)c2.x * 32 + lane];
        uint2 v3 = xw2[(size_t)c3.x * 32 + lane];
        float wa = __int_as_float(c0.y), wb = __int_as_float(c1.y);
        float wc_ = __int_as_float(c2.y), wd = __int_as_float(c3.y);
        float2 f;
        f = __half22float2(*(__half2*)&v0.x); a0 += wa * f.x; a1 += wa * f.y;
        f = __half22float2(*(__half2*)&v0.y); a2 += wa * f.x; a3 += wa * f.y;
        f = __half22float2(*(__half2*)&v1.x); a0 += wb * f.x; a1 += wb * f.y;
        f = __half22float2(*(__half2*)&v1.y); a2 += wb * f.x; a3 += wb * f.y;
        f = __half22float2(*(__half2*)&v2.x); a0 += wc_ * f.x; a1 += wc_ * f.y;
        f = __half22float2(*(__half2*)&v2.y); a2 += wc_ * f.x; a3 += wc_ * f.y;
        f = __half22float2(*(__half2*)&v3.x); a0 += wd * f.x; a1 += wd * f.y;
        f = __half22float2(*(__half2*)&v3.y); a2 += wd * f.x; a3 += wd * f.y;
    }
    for (; e < end; e++) {
        int2 c = g_csr[e];
        float w = __int_as_float(c.y);
        uint2 v = xw2[(size_t)c.x * 32 + lane];
        float2 f;
        f = __half22float2(*(__half2*)&v.x); a0 += w * f.x; a1 += w * f.y;
        f = __half22float2(*(__half2*)&v.y); a2 += w * f.x; a3 += w * f.y;
    }

    float4 bb = ((const float4*)b1)[lane];
    float h0 = fmaxf(a0 + bb.x, 0.f);
    float h1 = fmaxf(a1 + bb.y, 0.f);
    float h2 = fmaxf(a2 + bb.z, 0.f);
    float h3 = fmaxf(a3 + bb.w, 0.f);

    int c = lane * 4;
    float z0 = h0 * w2s[(c + 0) * 2 + 0] + h1 * w2s[(c + 1) * 2 + 0]
             + h2 * w2s[(c + 2) * 2 + 0] + h3 * w2s[(c + 3) * 2 + 0];
    float z1 = h0 * w2s[(c + 0) * 2 + 1] + h1 * w2s[(c + 1) * 2 + 1]
             + h2 * w2s[(c + 2) * 2 + 1] + h3 * w2s[(c + 3) * 2 + 1];
    #pragma unroll
    for (int off = 16; off > 0; off >>= 1) {
        z0 += __shfl_down_sync(0xffffffffu, z0, off);
        z1 += __shfl_down_sync(0xffffffffu, z1, off);
    }
    if (lane == 0) ((float2*)g_z)[i] = make_float2(z0, z1);
}

// ---------------- layer-2 aggregation + Wc + sigmoid ----------------
__global__ void k_agg2(const float* __restrict__ b2, const float* __restrict__ Wc,
                       const float* __restrict__ bc, float* __restrict__ out) {
    int i = blockIdx.x * blockDim.x + threadIdx.x;
    if (i >= NN) return;
    const float2* z2 = (const float2*)g_z;
    float di = g_dinv[i];
    float sn = di * di;
    float2 zi = z2[i];
    float a0 = zi.x * sn, a1 = zi.y * sn;
    int e = g_rowptr[i];
    int end = e + g_deg[i];
    for (; e < end; e++) {
        int2 c = g_csr[e];
        float w = __int_as_float(c.y);
        float2 zs = z2[c.x];
        a0 += w * zs.x;
        a1 += w * zs.y;
    }
    float h0 = fmaxf(a0 + b2[0], 0.f);
    float h1 = fmaxf(a1 + b2[1], 0.f);
    float o = h0 * Wc[0] + h1 * Wc[1] + bc[0];
    out[i] = 1.f / (1.f + expf(-o));
}

// ---------------- launch (single stream, no host objects) ----------------
extern "C" void kernel_launch(void* const* d_in, const int* in_sizes, int n_in,
                              void* d_out, int out_size) {
    const float* x  = (const float*)d_in[0];
    const int*   ei = (const int*)d_in[1];
    const float* W1 = (const float*)d_in[2];
    const float* b1 = (const float*)d_in[3];
    const float* W2 = (const float*)d_in[4];
    const float* b2 = (const float*)d_in[5];
    const float* Wc = (const float*)d_in[6];
    const float* bc = (const float*)d_in[7];
    float* out = (float*)d_out;

    k_init<<<(NN + 255) / 256, 256>>>();
    k_cvt_count<<<CVTX_NB + CVTW_NB + CNT_NB, 256>>>(x, W1, ei);
    k_scan<<<NBT, 512>>>();
    k_fill_gemm<<<GEMM_NB + FILL_NB, 256>>>(ei);
    k_agg1<<<(NN + 7) / 8, 256>>>(b1, W2);
    k_agg2<<<(NN + 255) / 256, 256>>>(b2, Wc, bc, out);
}

// round 15
// speedup vs baseline: 1.0005x; 1.0005x over previous
#include <cuda_runtime.h>
#include <cuda_fp16.h>
#include <cuda_bf16.h>
#include <mma.h>
#include <math.h>
#include <cstdint>

using namespace nvcuda;

#define NN 100000
#define NE 1600000
#define FEAT 165
#define HID 128
#define KPAD 192          // K padded to 6 tiles of 32
#define NKT 6
#define NBT 196           // scan tiles (196 * 512 >= NN)
#define GEMM_NB 1563      // ceil(100000/64)
#define FILL_NB 782       // 782*256 threads * 8 edges >= NE
#define CVTX_NB 18750     // 100000*192/4/256
#define CNT_NB 1563       // ceil(NE/4/256)

// ---------------- scratch (static __device__, allocation-free) ----------------
__device__ int            g_deg[NN];
__device__ float          g_dinv[NN];
__device__ int            g_rowptr[NN];
__device__ int            g_cursor[NN];
__device__ int            g_tile_ctr;
__device__ unsigned       g_tile_state[NBT];
__device__ int2           g_csr[NE];                     // (src, bits(w))
__device__ __nv_bfloat16  g_xb[(size_t)100096 * KPAD];   // x in bf16, padded
__device__ __nv_bfloat16  g_w1b[KPAD * HID];             // W1 in bf16, padded
__device__ __half         g_xw[(size_t)NN * HID];        // x @ W1 in fp16
__device__ float          g_z[NN * 2];

#define ST_AGG 0x40000000u
#define ST_PRE 0x80000000u
#define ST_VAL 0x3FFFFFFFu

// ---------------- cp.async helpers ----------------
__device__ __forceinline__ void cp_async16(uint32_t sdst, const void* gsrc) {
    asm volatile("cp.async.cg.shared.global [%0], [%1], 16;" :: "r"(sdst), "l"(gsrc));
}
__device__ __forceinline__ void cp_commit() {
    asm volatile("cp.async.commit_group;");
}
template <int N>
__device__ __forceinline__ void cp_wait() {
    asm volatile("cp.async.wait_group %0;" :: "n"(N));
}

// ---------------- init: zero degrees + scan state + W1 cvt ----------------
__global__ void k_init(const float* __restrict__ W1) {
    int i = blockIdx.x * blockDim.x + threadIdx.x;
    if (i < NN) g_deg[i] = 0;
    if (i < NBT) g_tile_state[i] = 0;
    if (i == 0) g_tile_ctr = 0;
    if (i < KPAD * HID / 4) {          // 6144 threads convert W1
        int k = i / (HID / 4);
        int n0 = (i % (HID / 4)) * 4;
        __nv_bfloat16 o[4];
        #pragma unroll
        for (int j = 0; j < 4; j++) {
            float v = (k < FEAT) ? W1[k * HID + n0 + j] : 0.f;
            o[j] = __float2bfloat16(v);
        }
        *(uint2*)&g_w1b[k * HID + n0] = *(uint2*)o;
    }
}

// ---------------- fused convert(x -> bf16) + degree count ----------------
__global__ void k_cvt_count(const float* __restrict__ x,
                            const int* __restrict__ ei) {
    int b = blockIdx.x;
    if (b < CVTX_NB) {
        int t = b * 256 + threadIdx.x;
        int r = t / (KPAD / 4);
        int k0 = (t % (KPAD / 4)) * 4;
        __nv_bfloat16 o[4];
        #pragma unroll
        for (int j = 0; j < 4; j++) {
            int k = k0 + j;
            float v = (k < FEAT) ? x[(size_t)r * FEAT + k] : 0.f;
            o[j] = __float2bfloat16(v);
        }
        *(uint2*)&g_xb[(size_t)r * KPAD + k0] = *(uint2*)o;
    } else {
        int t = (b - CVTX_NB) * 256 + threadIdx.x;
        int e0 = t * 4;
        if (e0 < NE) {
            int4 d4 = *(const int4*)&ei[NE + e0];
            if (d4.x >= 0 && d4.x < NN) atomicAdd(&g_deg[d4.x], 1);
            if (d4.y >= 0 && d4.y < NN) atomicAdd(&g_deg[d4.y], 1);
            if (d4.z >= 0 && d4.z < NN) atomicAdd(&g_deg[d4.z], 1);
            if (d4.w >= 0 && d4.w < NN) atomicAdd(&g_deg[d4.w], 1);
        }
    }
}

// ---------------- single-pass scan (decoupled lookback) + dinv ----------------
__global__ void k_scan() {
    __shared__ int s[512];
    __shared__ int sh_bid;
    __shared__ int sh_excl;
    int t = threadIdx.x;
    if (t == 0) sh_bid = atomicAdd(&g_tile_ctr, 1);
    __syncthreads();
    int bid = sh_bid;
    int i = bid * 512 + t;
    int v = (i < NN) ? g_deg[i] : 0;
    if (i < NN) g_dinv[i] = rsqrtf((float)v + 1.0f);
    s[t] = v;
    __syncthreads();
    #pragma unroll
    for (int off = 1; off < 512; off <<= 1) {
        int u = (t >= off) ? s[t - off] : 0;
        __syncthreads();
        s[t] += u;
        __syncthreads();
    }
    int incl = s[t];
    int total = s[511];
    if (t == 0) {
        if (bid == 0) {
            __threadfence();
            atomicExch(&g_tile_state[0], ST_PRE | (unsigned)total);
            sh_excl = 0;
        } else {
            __threadfence();
            atomicExch(&g_tile_state[bid], ST_AGG | (unsigned)total);
            int excl = 0;
            for (int j = bid - 1; j >= 0; j--) {
                unsigned st;
                do { st = atomicAdd(&g_tile_state[j], 0u); } while (!(st & (ST_AGG | ST_PRE)));
                excl += (int)(st & ST_VAL);
                if (st & ST_PRE) break;
            }
            __threadfence();
            atomicExch(&g_tile_state[bid], ST_PRE | (unsigned)(excl + total));
            sh_excl = excl;
        }
    }
    __syncthreads();
    if (i < NN) {
        int rp = sh_excl + incl - v;
        g_rowptr[i] = rp;
        g_cursor[i] = rp;
    }
}

// ---------------- fused fill + GEMM1 (cp.async 2-stage, 64x128 tile) --------
#define ASTR 40           // A row stride in bf16 (80B)
#define BSTR 136          // B row stride in bf16 (272B)
#define AS_SZ (64 * ASTR * 2)     // 5120 B
#define BS_SZ (32 * BSTR * 2)     // 8704 B
#define STAGE_SZ (AS_SZ + BS_SZ)  // 13824 B
#define SM_BYTES (2 * STAGE_SZ)   // 27648 B

__global__ __launch_bounds__(256, 3) void k_fill_gemm(const int* __restrict__ ei) {
    __shared__ __align__(16) char smraw[SM_BYTES];

    int tid = threadIdx.x;

    if (blockIdx.x >= GEMM_NB) {
        // ---------- fill branch: 8 edges per thread, int4 reads ----------
        int t8 = (blockIdx.x - GEMM_NB) * 256 + tid;
        int e0 = t8 * 8;
        if (e0 < NE) {
            int4 sa = *(const int4*)&ei[e0];
            int4 sb = *(const int4*)&ei[e0 + 4];
            int4 da = *(const int4*)&ei[NE + e0];
            int4 db = *(const int4*)&ei[NE + e0 + 4];
            int src[8] = {sa.x, sa.y, sa.z, sa.w, sb.x, sb.y, sb.z, sb.w};
            int dst[8] = {da.x, da.y, da.z, da.w, db.x, db.y, db.z, db.w};
            float ds[8], dd[8];
            #pragma unroll
            for (int j = 0; j < 8; j++) {
                bool ok = (src[j] >= 0 && src[j] < NN && dst[j] >= 0 && dst[j] < NN);
                ds[j] = ok ? g_dinv[src[j]] : 0.f;
                dd[j] = ok ? g_dinv[dst[j]] : 0.f;
                if (!ok) dst[j] = -1;
            }
            #pragma unroll
            for (int j = 0; j < 8; j++) {
                if (dst[j] >= 0) {
                    int p = atomicAdd(&g_cursor[dst[j]], 1);
                    g_csr[p] = make_int2(src[j], __float_as_int(ds[j] * dd[j]));
                }
            }
        }
        return;
    }

    // ---------- GEMM branch: 64x128 tile, 8 warps (2x4) of 32x32 ----------
    int w = tid >> 5;
    int lane = tid & 31;
    int warp_m = w & 1;        // 0..1 -> 32-row band
    int warp_n = w >> 1;       // 0..3 -> 32-col band
    int row0 = blockIdx.x * 64;

    uint32_t smb = (uint32_t)__cvta_generic_to_shared(smraw);

    // per-thread cp.async chunk coords (3 chunks: 1 for A, 2 for B)
    int a_m = tid >> 2, a_c = tid & 3;                 // A: 256 chunks
    int b_k[2], b_c[2];
    #pragma unroll
    for (int i = 0; i < 2; i++) {
        int c = tid + i * 256;                         // B: 512 chunks
        b_k[i] = c >> 4; b_c[i] = c & 15;
    }

    auto issueTile = [&](int kt, int stg) {
        uint32_t Ab = smb + stg * STAGE_SZ;
        uint32_t Bb = Ab + AS_SZ;
        cp_async16(Ab + a_m * (ASTR * 2) + a_c * 16,
                   &g_xb[(size_t)(row0 + a_m) * KPAD + kt * 32 + a_c * 8]);
        #pragma unroll
        for (int i = 0; i < 2; i++)
            cp_async16(Bb + b_k[i] * (BSTR * 2) + b_c[i] * 16,
                       &g_w1b[(kt * 32 + b_k[i]) * HID + b_c[i] * 8]);
        cp_commit();
    };

    wmma::fragment<wmma::accumulator, 16, 16, 16, float> cf[2][2];
    #pragma unroll
    for (int mi = 0; mi < 2; mi++)
        #pragma unroll
        for (int ni = 0; ni < 2; ni++)
            wmma::fill_fragment(cf[mi][ni], 0.0f);

    issueTile(0, 0);
    for (int kt = 0; kt < NKT; kt++) {
        int stg = kt & 1;
        if (kt + 1 < NKT) {
            issueTile(kt + 1, stg ^ 1);
            cp_wait<1>();
        } else {
            cp_wait<0>();
        }
        __syncthreads();   // tile kt visible to all warps

        const __nv_bfloat16* As = (const __nv_bfloat16*)(smraw + stg * STAGE_SZ);
        const __nv_bfloat16* Bs = (const __nv_bfloat16*)(smraw + stg * STAGE_SZ + AS_SZ);
        #pragma unroll
        for (int ks = 0; ks < 2; ks++) {
            wmma::fragment<wmma::matrix_a, 16, 16, 16, __nv_bfloat16, wmma::row_major> af[2];
            wmma::fragment<wmma::matrix_b, 16, 16, 16, __nv_bfloat16, wmma::row_major> bf[2];
            #pragma unroll
            for (int mi = 0; mi < 2; mi++)
                wmma::load_matrix_sync(af[mi], As + (warp_m * 32 + mi * 16) * ASTR + ks * 16, ASTR);
            #pragma unroll
            for (int ni = 0; ni < 2; ni++)
                wmma::load_matrix_sync(bf[ni], Bs + (ks * 16) * BSTR + warp_n * 32 + ni * 16, BSTR);
            #pragma unroll
            for (int mi = 0; mi < 2; mi++)
                #pragma unroll
                for (int ni = 0; ni < 2; ni++)
                    wmma::mma_sync(cf[mi][ni], af[mi], bf[ni], cf[mi][ni]);
        }
        __syncthreads();   // all warps done with tile kt's buffer
    }

    // epilogue: per-fragment smem stage -> fp16 global (overlay smraw)
    float* Cs = (float*)smraw + w * 256;
    #pragma unroll
    for (int mi = 0; mi < 2; mi++) {
        #pragma unroll
        for (int ni = 0; ni < 2; ni++) {
            wmma::store_matrix_sync(Cs, cf[mi][ni], 16, wmma::mem_row_major);
            __syncwarp();
            int fr = lane >> 1;
            int fc = (lane & 1) * 8;
            int r = row0 + warp_m * 32 + mi * 16 + fr;
            if (r < NN) {
                const float* src = &Cs[fr * 16 + fc];
                __half2 h0 = __floats2half2_rn(src[0], src[1]);
                __half2 h1 = __floats2half2_rn(src[2], src[3]);
                __half2 h2 = __floats2half2_rn(src[4], src[5]);
                __half2 h3 = __floats2half2_rn(src[6], src[7]);
                uint4 pk;
                pk.x = *(unsigned*)&h0; pk.y = *(unsigned*)&h1;
                pk.z = *(unsigned*)&h2; pk.w = *(unsigned*)&h3;
                *(uint4*)&g_xw[(size_t)r * HID + warp_n * 32 + ni * 16 + fc] = pk;
            }
            __syncwarp();
        }
    }
}

// ---------------- layer-1 aggregation, fused bias+relu+(@W2) ----------------
__global__ __launch_bounds__(256) void k_agg1(const float* __restrict__ b1,
                                              const float* __restrict__ W2) {
    __shared__ float w2s[HID * 2];
    int t = threadIdx.x;
    w2s[t] = W2[t];
    __syncthreads();

    int warp = t >> 5, lane = t & 31;
    int i = blockIdx.x * 8 + warp;
    if (i >= NN) return;

    const uint2* xw2 = (const uint2*)g_xw;
    float di = g_dinv[i];
    float sn = di * di;
    uint2 sv = xw2[(size_t)i * 32 + lane];
    float2 s0 = __half22float2(*(__half2*)&sv.x);
    float2 s1 = __half22float2(*(__half2*)&sv.y);
    float a0 = sn * s0.x, a1 = sn * s0.y, a2 = sn * s1.x, a3 = sn * s1.y;

    int e = g_rowptr[i];
    int end = e + g_deg[i];
    for (; e + 4 <= end; e += 4) {
        int2 c0 = g_csr[e],     c1 = g_csr[e + 1];
        int2 c2 = g_csr[e + 2], c3 = g_csr[e + 3];
        uint2 v0 = xw2[(size_t)c0.x * 32 + lane];
        uint2 v1 = xw2[(size_t)c1.x * 32 + lane];
        uint2 v2 = xw2[(size_t)c2.x * 32 + lane];
        uint2 v3 = xw2[(size_t)c3.x * 32 + lane];
        float wa = __int_as_float(c0.y), wb = __int_as_float(c1.y);
        float wc_ = __int_as_float(c2.y), wd = __int_as_float(c3.y);
        float2 f;
        f = __half22float2(*(__half2*)&v0.x); a0 += wa * f.x; a1 += wa * f.y;
        f = __half22float2(*(__half2*)&v0.y); a2 += wa * f.x; a3 += wa * f.y;
        f = __half22float2(*(__half2*)&v1.x); a0 += wb * f.x; a1 += wb * f.y;
        f = __half22float2(*(__half2*)&v1.y); a2 += wb * f.x; a3 += wb * f.y;
        f = __half22float2(*(__half2*)&v2.x); a0 += wc_ * f.x; a1 += wc_ * f.y;
        f = __half22float2(*(__half2*)&v2.y); a2 += wc_ * f.x; a3 += wc_ * f.y;
        f = __half22float2(*(__half2*)&v3.x); a0 += wd * f.x; a1 += wd * f.y;
        f = __half22float2(*(__half2*)&v3.y); a2 += wd * f.x; a3 += wd * f.y;
    }
    for (; e < end; e++) {
        int2 c = g_csr[e];
        float w = __int_as_float(c.y);
        uint2 v = xw2[(size_t)c.x * 32 + lane];
        float2 f;
        f = __half22float2(*(__half2*)&v.x); a0 += w * f.x; a1 += w * f.y;
        f = __half22float2(*(__half2*)&v.y); a2 += w * f.x; a3 += w * f.y;
    }

    float4 bb = ((const float4*)b1)[lane];
    float h0 = fmaxf(a0 + bb.x, 0.f);
    float h1 = fmaxf(a1 + bb.y, 0.f);
    float h2 = fmaxf(a2 + bb.z, 0.f);
    float h3 = fmaxf(a3 + bb.w, 0.f);

    int c = lane * 4;
    float z0 = h0 * w2s[(c + 0) * 2 + 0] + h1 * w2s[(c + 1) * 2 + 0]
             + h2 * w2s[(c + 2) * 2 + 0] + h3 * w2s[(c + 3) * 2 + 0];
    float z1 = h0 * w2s[(c + 0) * 2 + 1] + h1 * w2s[(c + 1) * 2 + 1]
             + h2 * w2s[(c + 2) * 2 + 1] + h3 * w2s[(c + 3) * 2 + 1];
    #pragma unroll
    for (int off = 16; off > 0; off >>= 1) {
        z0 += __shfl_down_sync(0xffffffffu, z0, off);
        z1 += __shfl_down_sync(0xffffffffu, z1, off);
    }
    if (lane == 0) ((float2*)g_z)[i] = make_float2(z0, z1);
}

// ---------------- layer-2 aggregation + Wc + sigmoid ----------------
__global__ void k_agg2(const float* __restrict__ b2, const float* __restrict__ Wc,
                       const float* __restrict__ bc, float* __restrict__ out) {
    int i = blockIdx.x * blockDim.x + threadIdx.x;
    if (i >= NN) return;
    const float2* z2 = (const float2*)g_z;
    float di = g_dinv[i];
    float sn = di * di;
    float2 zi = z2[i];
    float a0 = zi.x * sn, a1 = zi.y * sn;
    int e = g_rowptr[i];
    int end = e + g_deg[i];
    for (; e < end; e++) {
        int2 c = g_csr[e];
        float w = __int_as_float(c.y);
        float2 zs = z2[c.x];
        a0 += w * zs.x;
        a1 += w * zs.y;
    }
    float h0 = fmaxf(a0 + b2[0], 0.f);
    float h1 = fmaxf(a1 + b2[1], 0.f);
    float o = h0 * Wc[0] + h1 * Wc[1] + bc[0];
    out[i] = 1.f / (1.f + expf(-o));
}

// ---------------- launch (single stream, no host objects) ----------------
extern "C" void kernel_launch(void* const* d_in, const int* in_sizes, int n_in,
                              void* d_out, int out_size) {
    const float* x  = (const float*)d_in[0];
    const int*   ei = (const int*)d_in[1];
    const float* W1 = (const float*)d_in[2];
    const float* b1 = (const float*)d_in[3];
    const float* W2 = (const float*)d_in[4];
    const float* b2 = (const float*)d_in[5];
    const float* Wc = (const float*)d_in[6];
    const float* bc = (const float*)d_in[7];
    float* out = (float*)d_out;

    k_init<<<(NN + 255) / 256, 256>>>(W1);
    k_cvt_count<<<CVTX_NB + CNT_NB, 256>>>(x, ei);
    k_scan<<<NBT, 512>>>();
    k_fill_gemm<<<GEMM_NB + FILL_NB, 256>>>(ei);
    k_agg1<<<(NN + 7) / 8, 256>>>(b1, W2);
    k_agg2<<<(NN + 255) / 256, 256>>>(b2, Wc, bc, out);
}

// round 16
// speedup vs baseline: 1.0602x; 1.0597x over previous
#include <cuda_runtime.h>
#include <cuda_fp16.h>
#include <cuda_bf16.h>
#include <mma.h>
#include <math.h>
#include <cstdint>

using namespace nvcuda;

#define NN 100000
#define NE 1600000
#define FEAT 165
#define HID 128
#define KPAD 192          // K padded to 6 tiles of 32
#define NKT 6
#define NBT 196           // scan tiles
#define GEMM_NB 1563      // ceil(100000/64)
#define CNT_NB 1563       // 1563*256*4 >= NE
#define FILL_NB 782       // 782*256*8 >= NE

// ---------------- scratch ----------------
__device__ int            g_deg[NN];
__device__ float          g_dinv[NN];
__device__ int            g_rowptr[NN];
__device__ int            g_cursor[NN];
__device__ int            g_tile_ctr;
__device__ unsigned       g_tile_state[NBT];
__device__ int2           g_csr[NE];              // (src, bits(w))
__device__ __nv_bfloat16  g_w1b[KPAD * HID];      // W1 bf16, zero-padded
__device__ __half         g_xw[(size_t)NN * HID]; // x @ W1 in fp16
__device__ float          g_z[NN * 2];

#define ST_AGG 0x40000000u
#define ST_PRE 0x80000000u
#define ST_VAL 0x3FFFFFFFu

// ---------------- cp.async helpers ----------------
__device__ __forceinline__ void cp_async4(uint32_t sdst, const void* gsrc) {
    asm volatile("cp.async.ca.shared.global [%0], [%1], 4;" :: "r"(sdst), "l"(gsrc));
}
__device__ __forceinline__ void cp_async16(uint32_t sdst, const void* gsrc) {
    asm volatile("cp.async.cg.shared.global [%0], [%1], 16;" :: "r"(sdst), "l"(gsrc));
}
__device__ __forceinline__ void cp_commit() {
    asm volatile("cp.async.commit_group;");
}
template <int N>
__device__ __forceinline__ void cp_wait() {
    asm volatile("cp.async.wait_group %0;" :: "n"(N));
}

// ---------------- init: zero deg + scan state + W1 -> bf16 ----------------
__global__ void k_init(const float* __restrict__ W1) {
    int i = blockIdx.x * blockDim.x + threadIdx.x;
    if (i < NN) g_deg[i] = 0;
    if (i < NBT) g_tile_state[i] = 0;
    if (i == 0) g_tile_ctr = 0;
    if (i < KPAD * HID / 4) {
        int k = i / (HID / 4);
        int n0 = (i % (HID / 4)) * 4;
        __nv_bfloat16 o[4];
        #pragma unroll
        for (int j = 0; j < 4; j++) {
            float v = (k < FEAT) ? W1[k * HID + n0 + j] : 0.f;
            o[j] = __float2bfloat16(v);
        }
        *(uint2*)&g_w1b[k * HID + n0] = *(uint2*)o;
    }
}

// ---------------- fused degree-count + GEMM1 (interleaved odd/even) ---------
// GEMM: 64x128 block tile, 8 warps of 32x32; fp32 x staged + converted on-chip
#define AFSTR 33                       // fp32 A stage row stride (words)
#define ASTR 40                        // bf16 A row stride
#define BSTR 136                       // bf16 B row stride

__global__ __launch_bounds__(256, 3) void k_cnt_gemm(const float* __restrict__ x,
                                                     const int* __restrict__ ei) {
    __shared__ __align__(16) float          Af[64 * AFSTR];       // 8448 B (single stage)
    __shared__ __align__(16) __nv_bfloat16  AsBf[2][64 * ASTR];   // 10240 B
    __shared__ __align__(16) __nv_bfloat16  Bs[2][32 * BSTR];     // 17408 B

    int tid = threadIdx.x;
    int bid = blockIdx.x;

    if (bid & 1) {
        // ---------- count branch: 4 edges per thread ----------
        int t = (bid >> 1) * 256 + tid;
        int e0 = t * 4;
        if (e0 < NE) {
            int4 d4 = *(const int4*)&ei[NE + e0];
            if (d4.x >= 0 && d4.x < NN) atomicAdd(&g_deg[d4.x], 1);
            if (d4.y >= 0 && d4.y < NN) atomicAdd(&g_deg[d4.y], 1);
            if (d4.z >= 0 && d4.z < NN) atomicAdd(&g_deg[d4.z], 1);
            if (d4.w >= 0 && d4.w < NN) atomicAdd(&g_deg[d4.w], 1);
        }
        return;
    }

    // ---------- GEMM branch ----------
    int w = tid >> 5;
    int lane = tid & 31;
    int warp_m = w & 1;        // 0..1 -> 32-row band
    int warp_n = w >> 1;       // 0..3 -> 32-col band
    int row0 = (bid >> 1) * 64;

    uint32_t afb = (uint32_t)__cvta_generic_to_shared(Af);
    uint32_t bsb = (uint32_t)__cvta_generic_to_shared(&Bs[0][0]);

    // A fp32 load mapping (coalesced): warp wl handles rows wl, wl+8, ...; lane = k word
    int al_row0 = w;           // + 8*i
    // B chunk mapping: 512 16B chunks, 2 per thread
    int b_k[2], b_c[2];
    #pragma unroll
    for (int i = 0; i < 2; i++) {
        int c = tid + i * 256;
        b_k[i] = c >> 4; b_c[i] = c & 15;
    }
    // convert mapping: thread t -> row t>>2, words (t&3)*8 .. +7
    int cv_m = tid >> 2, cv_k0 = (tid & 3) * 8;

    auto issueTile = [&](int kt, int sB) {
        // A: fp32, predicated 4B cp.async
        int kk = kt * 32 + lane;
        bool kval = kk < FEAT;
        #pragma unroll
        for (int i = 0; i < 8; i++) {
            int m = al_row0 + i * 8;
            if (kval && (row0 + m) < NN)
                cp_async4(afb + (m * AFSTR + lane) * 4,
                          &x[(size_t)(row0 + m) * FEAT + kk]);
        }
        // B: bf16 16B chunks from g_w1b (zero-padded rows)
        #pragma unroll
        for (int i = 0; i < 2; i++)
            cp_async16(bsb + sB * (32 * BSTR * 2) + b_k[i] * (BSTR * 2) + b_c[i] * 16,
                       &g_w1b[(kt * 32 + b_k[i]) * HID + b_c[i] * 8]);
        cp_commit();
    };

    wmma::fragment<wmma::accumulator, 16, 16, 16, float> cf[2][2];
    #pragma unroll
    for (int mi = 0; mi < 2; mi++)
        #pragma unroll
        for (int ni = 0; ni < 2; ni++)
            wmma::fill_fragment(cf[mi][ni], 0.0f);

    issueTile(0, 0);
    for (int kt = 0; kt < NKT; kt++) {
        int sB = kt & 1;
        cp_wait<0>();
        __syncthreads();                   // Af + Bs[sB] ready

        // convert fp32 stage -> bf16 tile (8 elems/thread, one 16B STS)
        {
            bool rval = (row0 + cv_m) < NN;
            __nv_bfloat16 o[8];
            #pragma unroll
            for (int j = 0; j < 8; j++) {
                int kk = kt * 32 + cv_k0 + j;
                float v = (rval && kk < FEAT) ? Af[cv_m * AFSTR + cv_k0 + j] : 0.f;
                o[j] = __float2bfloat16(v);
            }
            *(uint4*)&AsBf[sB][cv_m * ASTR + cv_k0] = *(uint4*)o;
        }
        __syncthreads();                   // AsBf[sB] ready, Af free

        if (kt + 1 < NKT) issueTile(kt + 1, sB ^ 1);   // overlaps MMA below

        #pragma unroll
        for (int ks = 0; ks < 2; ks++) {
            wmma::fragment<wmma::matrix_a, 16, 16, 16, __nv_bfloat16, wmma::row_major> af[2];
            wmma::fragment<wmma::matrix_b, 16, 16, 16, __nv_bfloat16, wmma::row_major> bf[2];
            #pragma unroll
            for (int mi = 0; mi < 2; mi++)
                wmma::load_matrix_sync(af[mi], &AsBf[sB][(warp_m * 32 + mi * 16) * ASTR + ks * 16], ASTR);
            #pragma unroll
            for (int ni = 0; ni < 2; ni++)
                wmma::load_matrix_sync(bf[ni], &Bs[sB][(ks * 16) * BSTR + warp_n * 32 + ni * 16], BSTR);
            #pragma unroll
            for (int mi = 0; mi < 2; mi++)
                #pragma unroll
                for (int ni = 0; ni < 2; ni++)
                    wmma::mma_sync(cf[mi][ni], af[mi], bf[ni], cf[mi][ni]);
        }
    }
    __syncthreads();

    // epilogue: per-fragment stage in Af region -> fp16 global
    float* Cs = Af + w * 256;
    #pragma unroll
    for (int mi = 0; mi < 2; mi++) {
        #pragma unroll
        for (int ni = 0; ni < 2; ni++) {
            wmma::store_matrix_sync(Cs, cf[mi][ni], 16, wmma::mem_row_major);
            __syncwarp();
            int fr = lane >> 1;
            int fc = (lane & 1) * 8;
            int r = row0 + warp_m * 32 + mi * 16 + fr;
            if (r < NN) {
                const float* src = &Cs[fr * 16 + fc];
                __half2 h0 = __floats2half2_rn(src[0], src[1]);
                __half2 h1 = __floats2half2_rn(src[2], src[3]);
                __half2 h2 = __floats2half2_rn(src[4], src[5]);
                __half2 h3 = __floats2half2_rn(src[6], src[7]);
                uint4 pk;
                pk.x = *(unsigned*)&h0; pk.y = *(unsigned*)&h1;
                pk.z = *(unsigned*)&h2; pk.w = *(unsigned*)&h3;
                *(uint4*)&g_xw[(size_t)r * HID + warp_n * 32 + ni * 16 + fc] = pk;
            }
            __syncwarp();
        }
    }
}

// ---------------- single-pass scan (decoupled lookback) + dinv ----------------
__global__ void k_scan() {
    __shared__ int s[512];
    __shared__ int sh_bid;
    __shared__ int sh_excl;
    int t = threadIdx.x;
    if (t == 0) sh_bid = atomicAdd(&g_tile_ctr, 1);
    __syncthreads();
    int bid = sh_bid;
    int i = bid * 512 + t;
    int v = (i < NN) ? g_deg[i] : 0;
    if (i < NN) g_dinv[i] = rsqrtf((float)v + 1.0f);
    s[t] = v;
    __syncthreads();
    #pragma unroll
    for (int off = 1; off < 512; off <<= 1) {
        int u = (t >= off) ? s[t - off] : 0;
        __syncthreads();
        s[t] += u;
        __syncthreads();
    }
    int incl = s[t];
    int total = s[511];
    if (t == 0) {
        if (bid == 0) {
            __threadfence();
            atomicExch(&g_tile_state[0], ST_PRE | (unsigned)total);
            sh_excl = 0;
        } else {
            __threadfence();
            atomicExch(&g_tile_state[bid], ST_AGG | (unsigned)total);
            int excl = 0;
            for (int j = bid - 1; j >= 0; j--) {
                unsigned st;
                do { st = atomicAdd(&g_tile_state[j], 0u); } while (!(st & (ST_AGG | ST_PRE)));
                excl += (int)(st & ST_VAL);
                if (st & ST_PRE) break;
            }
            __threadfence();
            atomicExch(&g_tile_state[bid], ST_PRE | (unsigned)(excl + total));
            sh_excl = excl;
        }
    }
    __syncthreads();
    if (i < NN) {
        int rp = sh_excl + incl - v;
        g_rowptr[i] = rp;
        g_cursor[i] = rp;
    }
}

// ---------------- CSR fill: 8 edges per thread, int4 reads ----------------
__global__ __launch_bounds__(256) void k_fill(const int* __restrict__ ei) {
    int t8 = blockIdx.x * 256 + threadIdx.x;
    int e0 = t8 * 8;
    if (e0 < NE) {
        int4 sa = *(const int4*)&ei[e0];
        int4 sb = *(const int4*)&ei[e0 + 4];
        int4 da = *(const int4*)&ei[NE + e0];
        int4 db = *(const int4*)&ei[NE + e0 + 4];
        int src[8] = {sa.x, sa.y, sa.z, sa.w, sb.x, sb.y, sb.z, sb.w};
        int dst[8] = {da.x, da.y, da.z, da.w, db.x, db.y, db.z, db.w};
        float ds[8], dd[8];
        #pragma unroll
        for (int j = 0; j < 8; j++) {
            bool ok = (src[j] >= 0 && src[j] < NN && dst[j] >= 0 && dst[j] < NN);
            ds[j] = ok ? g_dinv[src[j]] : 0.f;
            dd[j] = ok ? g_dinv[dst[j]] : 0.f;
            if (!ok) dst[j] = -1;
        }
        #pragma unroll
        for (int j = 0; j < 8; j++) {
            if (dst[j] >= 0) {
                int p = atomicAdd(&g_cursor[dst[j]], 1);
                g_csr[p] = make_int2(src[j], __float_as_int(ds[j] * dd[j]));
            }
        }
    }
}

// ---------------- layer-1 aggregation, fused bias+relu+(@W2) ----------------
__global__ __launch_bounds__(256) void k_agg1(const float* __restrict__ b1,
                                              const float* __restrict__ W2) {
    __shared__ float w2s[HID * 2];
    int t = threadIdx.x;
    w2s[t] = W2[t];
    __syncthreads();

    int warp = t >> 5, lane = t & 31;
    int i = blockIdx.x * 8 + warp;
    if (i >= NN) return;

    const uint2* xw2 = (const uint2*)g_xw;
    float di = g_dinv[i];
    float sn = di * di;
    uint2 sv = xw2[(size_t)i * 32 + lane];
    float2 s0 = __half22float2(*(__half2*)&sv.x);
    float2 s1 = __half22float2(*(__half2*)&sv.y);
    float a0 = sn * s0.x, a1 = sn * s0.y, a2 = sn * s1.x, a3 = sn * s1.y;

    int e = g_rowptr[i];
    int end = e + g_deg[i];
    for (; e + 4 <= end; e += 4) {
        int2 c0 = g_csr[e],     c1 = g_csr[e + 1];
        int2 c2 = g_csr[e + 2], c3 = g_csr[e + 3];
        uint2 v0 = xw2[(size_t)c0.x * 32 + lane];
        uint2 v1 = xw2[(size_t)c1.x * 32 + lane];
        uint2 v2 = xw2[(size_t)c2.x * 32 + lane];
        uint2 v3 = xw2[(size_t)c3.x * 32 + lane];
        float wa = __int_as_float(c0.y), wb = __int_as_float(c1.y);
        float wc_ = __int_as_float(c2.y), wd = __int_as_float(c3.y);
        float2 f;
        f = __half22float2(*(__half2*)&v0.x); a0 += wa * f.x; a1 += wa * f.y;
        f = __half22float2(*(__half2*)&v0.y); a2 += wa * f.x; a3 += wa * f.y;
        f = __half22float2(*(__half2*)&v1.x); a0 += wb * f.x; a1 += wb * f.y;
        f = __half22float2(*(__half2*)&v1.y); a2 += wb * f.x; a3 += wb * f.y;
        f = __half22float2(*(__half2*)&v2.x); a0 += wc_ * f.x; a1 += wc_ * f.y;
        f = __half22float2(*(__half2*)&v2.y); a2 += wc_ * f.x; a3 += wc_ * f.y;
        f = __half22float2(*(__half2*)&v3.x); a0 += wd * f.x; a1 += wd * f.y;
        f = __half22float2(*(__half2*)&v3.y); a2 += wd * f.x; a3 += wd * f.y;
    }
    for (; e < end; e++) {
        int2 c = g_csr[e];
        float w = __int_as_float(c.y);
        uint2 v = xw2[(size_t)c.x * 32 + lane];
        float2 f;
        f = __half22float2(*(__half2*)&v.x); a0 += w * f.x; a1 += w * f.y;
        f = __half22float2(*(__half2*)&v.y); a2 += w * f.x; a3 += w * f.y;
    }

    float4 bb = ((const float4*)b1)[lane];
    float h0 = fmaxf(a0 + bb.x, 0.f);
    float h1 = fmaxf(a1 + bb.y, 0.f);
    float h2 = fmaxf(a2 + bb.z, 0.f);
    float h3 = fmaxf(a3 + bb.w, 0.f);

    int c = lane * 4;
    float z0 = h0 * w2s[(c + 0) * 2 + 0] + h1 * w2s[(c + 1) * 2 + 0]
             + h2 * w2s[(c + 2) * 2 + 0] + h3 * w2s[(c + 3) * 2 + 0];
    float z1 = h0 * w2s[(c + 0) * 2 + 1] + h1 * w2s[(c + 1) * 2 + 1]
             + h2 * w2s[(c + 2) * 2 + 1] + h3 * w2s[(c + 3) * 2 + 1];
    #pragma unroll
    for (int off = 16; off > 0; off >>= 1) {
        z0 += __shfl_down_sync(0xffffffffu, z0, off);
        z1 += __shfl_down_sync(0xffffffffu, z1, off);
    }
    if (lane == 0) ((float2*)g_z)[i] = make_float2(z0, z1);
}

// ---------------- layer-2 aggregation + Wc + sigmoid ----------------
__global__ void k_agg2(const float* __restrict__ b2, const float* __restrict__ Wc,
                       const float* __restrict__ bc, float* __restrict__ out) {
    int i = blockIdx.x * blockDim.x + threadIdx.x;
    if (i >= NN) return;
    const float2* z2 = (const float2*)g_z;
    float di = g_dinv[i];
    float sn = di * di;
    float2 zi = z2[i];
    float a0 = zi.x * sn, a1 = zi.y * sn;
    int e = g_rowptr[i];
    int end = e + g_deg[i];
    for (; e < end; e++) {
        int2 c = g_csr[e];
        float w = __int_as_float(c.y);
        float2 zs = z2[c.x];
        a0 += w * zs.x;
        a1 += w * zs.y;
    }
    float h0 = fmaxf(a0 + b2[0], 0.f);
    float h1 = fmaxf(a1 + b2[1], 0.f);
    float o = h0 * Wc[0] + h1 * Wc[1] + bc[0];
    out[i] = 1.f / (1.f + expf(-o));
}

// ---------------- launch (single stream, no host objects) ----------------
extern "C" void kernel_launch(void* const* d_in, const int* in_sizes, int n_in,
                              void* d_out, int out_size) {
    const float* x  = (const float*)d_in[0];
    const int*   ei = (const int*)d_in[1];
    const float* W1 = (const float*)d_in[2];
    const float* b1 = (const float*)d_in[3];
    const float* W2 = (const float*)d_in[4];
    const float* b2 = (const float*)d_in[5];
    const float* Wc = (const float*)d_in[6];
    const float* bc = (const float*)d_in[7];
    float* out = (float*)d_out;

    k_init<<<(NN + 255) / 256, 256>>>(W1);
    k_cnt_gemm<<<GEMM_NB + CNT_NB, 256>>>(x, ei);
    k_scan<<<NBT, 512>>>();
    k_fill<<<FILL_NB, 256>>>(ei);
    k_agg1<<<(NN + 7) / 8, 256>>>(b1, W2);
    k_agg2<<<(NN + 255) / 256, 256>>>(b2, Wc, bc, out);
}

// round 17
// speedup vs baseline: 1.1122x; 1.0490x over previous
#include <cuda_runtime.h>
#include <cuda_fp16.h>
#include <cuda_bf16.h>
#include <mma.h>
#include <math.h>
#include <cstdint>

using namespace nvcuda;

#define NN 100000
#define NE 1600000
#define FEAT 165
#define HID 128
#define KPAD 192
#define NKT 6
#define NBT 196
#define GEMM_NB 1563      // ceil(100000/64)
#define CNT_NB 1563       // 1563*256*4 >= NE
#define FILL_NB 782       // 782*256*8 >= NE
#define CVTW_NB 24        // 24*256*4 = KPAD*HID
#define FG_NB 2346        // 1564 gemm (1 spare) + 782 fill, 2:1 interleave

// ---------------- scratch ----------------
__device__ int            g_deg[NN];           // ZERO-ON-EXIT invariant (agg2 clears)
__device__ float          g_dinv[NN];
__device__ int            g_rowptr[NN];
__device__ int            g_cursor[NN];
__device__ int            g_tile_ctr;
__device__ unsigned       g_tile_state[NBT];
__device__ int2           g_csr[NE];
__device__ __nv_bfloat16  g_w1b[KPAD * HID];
__device__ __half         g_xw[(size_t)NN * HID];
__device__ float          g_z[NN * 2];

#define ST_AGG 0x40000000u
#define ST_PRE 0x80000000u
#define ST_VAL 0x3FFFFFFFu

// ---------------- cp.async helpers ----------------
__device__ __forceinline__ void cp_async4(uint32_t sdst, const void* gsrc) {
    asm volatile("cp.async.ca.shared.global [%0], [%1], 4;" :: "r"(sdst), "l"(gsrc));
}
__device__ __forceinline__ void cp_async16(uint32_t sdst, const void* gsrc) {
    asm volatile("cp.async.cg.shared.global [%0], [%1], 16;" :: "r"(sdst), "l"(gsrc));
}
__device__ __forceinline__ void cp_commit() {
    asm volatile("cp.async.commit_group;");
}
template <int N>
__device__ __forceinline__ void cp_wait() {
    asm volatile("cp.async.wait_group %0;" :: "n"(N));
}

// ---------------- count + W1 cvt + scan-state reset (one launch) ------------
// blocks [0, CVTW_NB): W1 -> bf16 ; blocks [CVTW_NB, ...): 4 edges/thread count
// g_deg arrives zeroed (invariant); tile_state/ctr zeroed here.
__global__ __launch_bounds__(256) void k_cnt(const float* __restrict__ W1,
                                             const int* __restrict__ ei) {
    int bid = blockIdx.x;
    int tid = threadIdx.x;
    if (bid < NBT && tid == 0) g_tile_state[bid] = 0;
    if (bid == 0 && tid == 1) g_tile_ctr = 0;

    if (bid < CVTW_NB) {
        int i = bid * 256 + tid;       // 6144 threads x 4 elems
        int k = i / (HID / 4);
        int n0 = (i % (HID / 4)) * 4;
        __nv_bfloat16 o[4];
        #pragma unroll
        for (int j = 0; j < 4; j++) {
            float v = (k < FEAT) ? W1[k * HID + n0 + j] : 0.f;
            o[j] = __float2bfloat16(v);
        }
        *(uint2*)&g_w1b[k * HID + n0] = *(uint2*)o;
        return;
    }
    int t = (bid - CVTW_NB) * 256 + tid;
    int e0 = t * 4;
    if (e0 < NE) {
        int4 d4 = *(const int4*)&ei[NE + e0];
        if (d4.x >= 0 && d4.x < NN) atomicAdd(&g_deg[d4.x], 1);
        if (d4.y >= 0 && d4.y < NN) atomicAdd(&g_deg[d4.y], 1);
        if (d4.z >= 0 && d4.z < NN) atomicAdd(&g_deg[d4.z], 1);
        if (d4.w >= 0 && d4.w < NN) atomicAdd(&g_deg[d4.w], 1);
    }
}

// ---------------- single-pass scan (decoupled lookback) + dinv --------------
__global__ void k_scan() {
    __shared__ int s[512];
    __shared__ int sh_bid;
    __shared__ int sh_excl;
    int t = threadIdx.x;
    if (t == 0) sh_bid = atomicAdd(&g_tile_ctr, 1);
    __syncthreads();
    int bid = sh_bid;
    int i = bid * 512 + t;
    int v = (i < NN) ? g_deg[i] : 0;
    if (i < NN) g_dinv[i] = rsqrtf((float)v + 1.0f);
    s[t] = v;
    __syncthreads();
    #pragma unroll
    for (int off = 1; off < 512; off <<= 1) {
        int u = (t >= off) ? s[t - off] : 0;
        __syncthreads();
        s[t] += u;
        __syncthreads();
    }
    int incl = s[t];
    int total = s[511];
    if (t == 0) {
        if (bid == 0) {
            __threadfence();
            atomicExch(&g_tile_state[0], ST_PRE | (unsigned)total);
            sh_excl = 0;
        } else {
            __threadfence();
            atomicExch(&g_tile_state[bid], ST_AGG | (unsigned)total);
            int excl = 0;
            for (int j = bid - 1; j >= 0; j--) {
                unsigned st;
                do { st = atomicAdd(&g_tile_state[j], 0u); } while (!(st & (ST_AGG | ST_PRE)));
                excl += (int)(st & ST_VAL);
                if (st & ST_PRE) break;
            }
            __threadfence();
            atomicExch(&g_tile_state[bid], ST_PRE | (unsigned)(excl + total));
            sh_excl = excl;
        }
    }
    __syncthreads();
    if (i < NN) {
        int rp = sh_excl + incl - v;
        g_rowptr[i] = rp;
        g_cursor[i] = rp;
    }
}

// ---------------- fused CSR-fill + GEMM1 (2:1 interleaved blocks) -----------
#define AFSTR 33
#define ASTR 40
#define BSTR 136

__global__ __launch_bounds__(256, 3) void k_fill_gemm(const float* __restrict__ x,
                                                      const int* __restrict__ ei) {
    __shared__ __align__(16) float          Af[64 * AFSTR];
    __shared__ __align__(16) __nv_bfloat16  AsBf[2][64 * ASTR];
    __shared__ __align__(16) __nv_bfloat16  Bs[2][32 * BSTR];

    int tid = threadIdx.x;
    int bid = blockIdx.x;

    if (bid % 3 == 2) {
        // ---------- fill branch: 8 edges per thread ----------
        int t8 = ((bid - 2) / 3) * 256 + tid;
        int e0 = t8 * 8;
        if (e0 < NE) {
            int4 sa = *(const int4*)&ei[e0];
            int4 sb = *(const int4*)&ei[e0 + 4];
            int4 da = *(const int4*)&ei[NE + e0];
            int4 db = *(const int4*)&ei[NE + e0 + 4];
            int src[8] = {sa.x, sa.y, sa.z, sa.w, sb.x, sb.y, sb.z, sb.w};
            int dst[8] = {da.x, da.y, da.z, da.w, db.x, db.y, db.z, db.w};
            float ds[8], dd[8];
            #pragma unroll
            for (int j = 0; j < 8; j++) {
                bool ok = (src[j] >= 0 && src[j] < NN && dst[j] >= 0 && dst[j] < NN);
                ds[j] = ok ? g_dinv[src[j]] : 0.f;
                dd[j] = ok ? g_dinv[dst[j]] : 0.f;
                if (!ok) dst[j] = -1;
            }
            #pragma unroll
            for (int j = 0; j < 8; j++) {
                if (dst[j] >= 0) {
                    int p = atomicAdd(&g_cursor[dst[j]], 1);
                    g_csr[p] = make_int2(src[j], __float_as_int(ds[j] * dd[j]));
                }
            }
        }
        return;
    }

    // ---------- GEMM branch: gemm_id = (bid/3)*2 + bid%3 ----------
    int gemm_id = (bid / 3) * 2 + (bid % 3);
    int row0 = gemm_id * 64;
    if (row0 >= NN + 63) { }          // spare block falls through with guards

    int w = tid >> 5;
    int lane = tid & 31;
    int warp_m = w & 1;
    int warp_n = w >> 1;

    uint32_t afb = (uint32_t)__cvta_generic_to_shared(Af);
    uint32_t bsb = (uint32_t)__cvta_generic_to_shared(&Bs[0][0]);

    int al_row0 = w;
    int b_k[2], b_c[2];
    #pragma unroll
    for (int i = 0; i < 2; i++) {
        int c = tid + i * 256;
        b_k[i] = c >> 4; b_c[i] = c & 15;
    }
    int cv_m = tid >> 2, cv_k0 = (tid & 3) * 8;

    auto issueTile = [&](int kt, int sB) {
        int kk = kt * 32 + lane;
        bool kval = kk < FEAT;
        #pragma unroll
        for (int i = 0; i < 8; i++) {
            int m = al_row0 + i * 8;
            if (kval && (row0 + m) < NN)
                cp_async4(afb + (m * AFSTR + lane) * 4,
                          &x[(size_t)(row0 + m) * FEAT + kk]);
        }
        #pragma unroll
        for (int i = 0; i < 2; i++)
            cp_async16(bsb + sB * (32 * BSTR * 2) + b_k[i] * (BSTR * 2) + b_c[i] * 16,
                       &g_w1b[(kt * 32 + b_k[i]) * HID + b_c[i] * 8]);
        cp_commit();
    };

    wmma::fragment<wmma::accumulator, 16, 16, 16, float> cf[2][2];
    #pragma unroll
    for (int mi = 0; mi < 2; mi++)
        #pragma unroll
        for (int ni = 0; ni < 2; ni++)
            wmma::fill_fragment(cf[mi][ni], 0.0f);

    issueTile(0, 0);
    for (int kt = 0; kt < NKT; kt++) {
        int sB = kt & 1;
        cp_wait<0>();
        __syncthreads();

        {
            bool rval = (row0 + cv_m) < NN;
            __nv_bfloat16 o[8];
            #pragma unroll
            for (int j = 0; j < 8; j++) {
                int kk = kt * 32 + cv_k0 + j;
                float v = (rval && kk < FEAT) ? Af[cv_m * AFSTR + cv_k0 + j] : 0.f;
                o[j] = __float2bfloat16(v);
            }
            *(uint4*)&AsBf[sB][cv_m * ASTR + cv_k0] = *(uint4*)o;
        }
        __syncthreads();

        if (kt + 1 < NKT) issueTile(kt + 1, sB ^ 1);

        #pragma unroll
        for (int ks = 0; ks < 2; ks++) {
            wmma::fragment<wmma::matrix_a, 16, 16, 16, __nv_bfloat16, wmma::row_major> af[2];
            wmma::fragment<wmma::matrix_b, 16, 16, 16, __nv_bfloat16, wmma::row_major> bf[2];
            #pragma unroll
            for (int mi = 0; mi < 2; mi++)
                wmma::load_matrix_sync(af[mi], &AsBf[sB][(warp_m * 32 + mi * 16) * ASTR + ks * 16], ASTR);
            #pragma unroll
            for (int ni = 0; ni < 2; ni++)
                wmma::load_matrix_sync(bf[ni], &Bs[sB][(ks * 16) * BSTR + warp_n * 32 + ni * 16], BSTR);
            #pragma unroll
            for (int mi = 0; mi < 2; mi++)
                #pragma unroll
                for (int ni = 0; ni < 2; ni++)
                    wmma::mma_sync(cf[mi][ni], af[mi], bf[ni], cf[mi][ni]);
        }
    }
    __syncthreads();

    float* Cs = Af + w * 256;
    #pragma unroll
    for (int mi = 0; mi < 2; mi++) {
        #pragma unroll
        for (int ni = 0; ni < 2; ni++) {
            wmma::store_matrix_sync(Cs, cf[mi][ni], 16, wmma::mem_row_major);
            __syncwarp();
            int fr = lane >> 1;
            int fc = (lane & 1) * 8;
            int r = row0 + warp_m * 32 + mi * 16 + fr;
            if (r < NN) {
                const float* src = &Cs[fr * 16 + fc];
                __half2 h0 = __floats2half2_rn(src[0], src[1]);
                __half2 h1 = __floats2half2_rn(src[2], src[3]);
                __half2 h2 = __floats2half2_rn(src[4], src[5]);
                __half2 h3 = __floats2half2_rn(src[6], src[7]);
                uint4 pk;
                pk.x = *(unsigned*)&h0; pk.y = *(unsigned*)&h1;
                pk.z = *(unsigned*)&h2; pk.w = *(unsigned*)&h3;
                *(uint4*)&g_xw[(size_t)r * HID + warp_n * 32 + ni * 16 + fc] = pk;
            }
            __syncwarp();
        }
    }
}

// ---------------- layer-1 aggregation, fused bias+relu+(@W2) ----------------
__global__ __launch_bounds__(256) void k_agg1(const float* __restrict__ b1,
                                              const float* __restrict__ W2) {
    __shared__ float w2s[HID * 2];
    int t = threadIdx.x;
    w2s[t] = W2[t];
    __syncthreads();

    int warp = t >> 5, lane = t & 31;
    int i = blockIdx.x * 8 + warp;
    if (i >= NN) return;

    const uint2* xw2 = (const uint2*)g_xw;
    float di = g_dinv[i];
    float sn = di * di;
    uint2 sv = xw2[(size_t)i * 32 + lane];
    float2 s0 = __half22float2(*(__half2*)&sv.x);
    float2 s1 = __half22float2(*(__half2*)&sv.y);
    float a0 = sn * s0.x, a1 = sn * s0.y, a2 = sn * s1.x, a3 = sn * s1.y;

    int e = g_rowptr[i];
    int end = e + g_deg[i];
    for (; e + 4 <= end; e += 4) {
        int2 c0 = g_csr[e],     c1 = g_csr[e + 1];
        int2 c2 = g_csr[e + 2], c3 = g_csr[e + 3];
        uint2 v0 = xw2[(size_t)c0.x * 32 + lane];
        uint2 v1 = xw2[(size_t)c1.x * 32 + lane];
        uint2 v2 = xw2[(size_t)c2.x * 32 + lane];
        uint2 v3 = xw2[(size_t)c3.x * 32 + lane];
        float wa = __int_as_float(c0.y), wb = __int_as_float(c1.y);
        float wc_ = __int_as_float(c2.y), wd = __int_as_float(c3.y);
        float2 f;
        f = __half22float2(*(__half2*)&v0.x); a0 += wa * f.x; a1 += wa * f.y;
        f = __half22float2(*(__half2*)&v0.y); a2 += wa * f.x; a3 += wa * f.y;
        f = __half22float2(*(__half2*)&v1.x); a0 += wb * f.x; a1 += wb * f.y;
        f = __half22float2(*(__half2*)&v1.y); a2 += wb * f.x; a3 += wb * f.y;
        f = __half22float2(*(__half2*)&v2.x); a0 += wc_ * f.x; a1 += wc_ * f.y;
        f = __half22float2(*(__half2*)&v2.y); a2 += wc_ * f.x; a3 += wc_ * f.y;
        f = __half22float2(*(__half2*)&v3.x); a0 += wd * f.x; a1 += wd * f.y;
        f = __half22float2(*(__half2*)&v3.y); a2 += wd * f.x; a3 += wd * f.y;
    }
    for (; e < end; e++) {
        int2 c = g_csr[e];
        float w = __int_as_float(c.y);
        uint2 v = xw2[(size_t)c.x * 32 + lane];
        float2 f;
        f = __half22float2(*(__half2*)&v.x); a0 += w * f.x; a1 += w * f.y;
        f = __half22float2(*(__half2*)&v.y); a2 += w * f.x; a3 += w * f.y;
    }

    float4 bb = ((const float4*)b1)[lane];
    float h0 = fmaxf(a0 + bb.x, 0.f);
    float h1 = fmaxf(a1 + bb.y, 0.f);
    float h2 = fmaxf(a2 + bb.z, 0.f);
    float h3 = fmaxf(a3 + bb.w, 0.f);

    int c = lane * 4;
    float z0 = h0 * w2s[(c + 0) * 2 + 0] + h1 * w2s[(c + 1) * 2 + 0]
             + h2 * w2s[(c + 2) * 2 + 0] + h3 * w2s[(c + 3) * 2 + 0];
    float z1 = h0 * w2s[(c + 0) * 2 + 1] + h1 * w2s[(c + 1) * 2 + 1]
             + h2 * w2s[(c + 2) * 2 + 1] + h3 * w2s[(c + 3) * 2 + 1];
    #pragma unroll
    for (int off = 16; off > 0; off >>= 1) {
        z0 += __shfl_down_sync(0xffffffffu, z0, off);
        z1 += __shfl_down_sync(0xffffffffu, z1, off);
    }
    if (lane == 0) ((float2*)g_z)[i] = make_float2(z0, z1);
}

// ---------------- layer-2 aggregation + Wc + sigmoid; restores g_deg=0 ------
__global__ void k_agg2(const float* __restrict__ b2, const float* __restrict__ Wc,
                       const float* __restrict__ bc, float* __restrict__ out) {
    int i = blockIdx.x * blockDim.x + threadIdx.x;
    if (i >= NN) return;
    const float2* z2 = (const float2*)g_z;
    float di = g_dinv[i];
    float sn = di * di;
    float2 zi = z2[i];
    float a0 = zi.x * sn, a1 = zi.y * sn;
    int e = g_rowptr[i];
    int end = e + g_deg[i];
    g_deg[i] = 0;                      // restore zero-on-exit invariant
    for (; e < end; e++) {
        int2 c = g_csr[e];
        float w = __int_as_float(c.y);
        float2 zs = z2[c.x];
        a0 += w * zs.x;
        a1 += w * zs.y;
    }
    float h0 = fmaxf(a0 + b2[0], 0.f);
    float h1 = fmaxf(a1 + b2[1], 0.f);
    float o = h0 * Wc[0] + h1 * Wc[1] + bc[0];
    out[i] = 1.f / (1.f + expf(-o));
}

// ---------------- launch (single stream, no host objects) ----------------
extern "C" void kernel_launch(void* const* d_in, const int* in_sizes, int n_in,
                              void* d_out, int out_size) {
    const float* x  = (const float*)d_in[0];
    const int*   ei = (const int*)d_in[1];
    const float* W1 = (const float*)d_in[2];
    const float* b1 = (const float*)d_in[3];
    const float* W2 = (const float*)d_in[4];
    const float* b2 = (const float*)d_in[5];
    const float* Wc = (const float*)d_in[6];
    const float* bc = (const float*)d_in[7];
    float* out = (float*)d_out;

    k_cnt<<<CVTW_NB + CNT_NB, 256>>>(W1, ei);
    k_scan<<<NBT, 512>>>();
    k_fill_gemm<<<FG_NB, 256>>>(x, ei);
    k_agg1<<<(NN + 7) / 8, 256>>>(b1, W2);
    k_agg2<<<(NN + 255) / 256, 256>>>(b2, Wc, bc, out);
}